// round 1
// baseline (speedup 1.0000x reference)
#include <cuda_runtime.h>
#include <math.h>

// Problem constants
#define ROWS   4096      // B*T
#define DMODEL 1024
#define TSEQ   2048
#define DK     64
#define NGRP   32        // B*H
#define OUT_ELEMS 4194304        // 2*2048*1024
#define ATTN_PER_G 4194304       // 2048*2048
#define GRP_STRIDE 131072        // T*dk

// Scratch (static __device__ — no allocation allowed)
__device__ float g_xn[ROWS * DMODEL];
__device__ float g_q [ROWS * DMODEL];
__device__ float g_k [ROWS * DMODEL];
__device__ float g_v [ROWS * DMODEL];

// ---------------------------------------------------------------------------
// scale_norm over a row of 1024: y = x * scale / max(||x||, 1e-5)
// one block per row, 256 threads, float4 per thread
// ---------------------------------------------------------------------------
__global__ __launch_bounds__(256) void scalenorm_kernel(
    const float* __restrict__ in, float* __restrict__ out,
    const float* __restrict__ scale_p)
{
    int row = blockIdx.x;
    int tid = threadIdx.x;
    const float4* rin  = (const float4*)in  + (size_t)row * (DMODEL / 4);
    float4*       rout = (float4*)out       + (size_t)row * (DMODEL / 4);

    float4 f = rin[tid];
    float ssq = f.x * f.x + f.y * f.y + f.z * f.z + f.w * f.w;

    #pragma unroll
    for (int o = 16; o > 0; o >>= 1) ssq += __shfl_xor_sync(0xffffffffu, ssq, o);

    __shared__ float ws[8];
    int w = tid >> 5, l = tid & 31;
    if (l == 0) ws[w] = ssq;
    __syncthreads();
    if (w == 0) {
        float s = (l < 8) ? ws[l] : 0.0f;
        #pragma unroll
        for (int o = 4; o > 0; o >>= 1) s += __shfl_xor_sync(0xffffffffu, s, o);
        if (l == 0) ws[0] = s;
    }
    __syncthreads();

    float n = sqrtf(ws[0]);
    float factor = scale_p[0] / fmaxf(n, 1e-5f);
    f.x *= factor; f.y *= factor; f.z *= factor; f.w *= factor;
    rout[tid] = f;
}

// ---------------------------------------------------------------------------
// SGEMM NT: C = alpha * (A[M,K] x B[N,K]^T) + bias[N]
// Both A and B are K-contiguous (row-major). 128x128 tile, BK=16,
// 256 threads, 8x8 per thread, float4 smem reads. Batched via blockIdx.z.
// M,N divisible by 128; K divisible by 16 (holds for all uses here).
// ---------------------------------------------------------------------------
__global__ __launch_bounds__(256) void sgemm_nt(
    const float* __restrict__ A, const float* __restrict__ B,
    const float* __restrict__ bias, float* __restrict__ C,
    int M, int N, int K,
    long strideA, long strideB, long strideC, float alpha)
{
    A += (long)blockIdx.z * strideA;
    B += (long)blockIdx.z * strideB;
    C += (long)blockIdx.z * strideC;

    __shared__ float As[16][128];
    __shared__ float Bs[16][128];

    int tid  = threadIdx.x;
    int tRow = tid / 16;           // 0..15 -> output row group
    int tCol = tid % 16;           // 0..15 -> output col group
    int rowBase = blockIdx.y * 128;
    int colBase = blockIdx.x * 128;

    int lRow = tid / 4;            // 0..63  loader row
    int lCol = (tid % 4) * 4;      // 0,4,8,12 loader k-offset

    float acc[8][8];
    #pragma unroll
    for (int i = 0; i < 8; i++)
        #pragma unroll
        for (int j = 0; j < 8; j++) acc[i][j] = 0.0f;

    for (int k0 = 0; k0 < K; k0 += 16) {
        #pragma unroll
        for (int p = 0; p < 2; p++) {
            int r = lRow + p * 64;
            float4 a = *(const float4*)(A + (size_t)(rowBase + r) * K + k0 + lCol);
            As[lCol + 0][r] = a.x;
            As[lCol + 1][r] = a.y;
            As[lCol + 2][r] = a.z;
            As[lCol + 3][r] = a.w;
            float4 b = *(const float4*)(B + (size_t)(colBase + r) * K + k0 + lCol);
            Bs[lCol + 0][r] = b.x;
            Bs[lCol + 1][r] = b.y;
            Bs[lCol + 2][r] = b.z;
            Bs[lCol + 3][r] = b.w;
        }
        __syncthreads();

        #pragma unroll
        for (int kk = 0; kk < 16; kk++) {
            float4 a0 = *(const float4*)&As[kk][tRow * 8];
            float4 a1 = *(const float4*)&As[kk][tRow * 8 + 4];
            float4 b0 = *(const float4*)&Bs[kk][tCol * 8];
            float4 b1 = *(const float4*)&Bs[kk][tCol * 8 + 4];
            float ra[8] = {a0.x, a0.y, a0.z, a0.w, a1.x, a1.y, a1.z, a1.w};
            float rb[8] = {b0.x, b0.y, b0.z, b0.w, b1.x, b1.y, b1.z, b1.w};
            #pragma unroll
            for (int i = 0; i < 8; i++)
                #pragma unroll
                for (int j = 0; j < 8; j++)
                    acc[i][j] = fmaf(ra[i], rb[j], acc[i][j]);
        }
        __syncthreads();
    }

    #pragma unroll
    for (int i = 0; i < 8; i++) {
        int r = rowBase + tRow * 8 + i;
        #pragma unroll
        for (int j4 = 0; j4 < 2; j4++) {
            int c = colBase + tCol * 8 + j4 * 4;
            float4 v;
            v.x = acc[i][j4 * 4 + 0] * alpha;
            v.y = acc[i][j4 * 4 + 1] * alpha;
            v.z = acc[i][j4 * 4 + 2] * alpha;
            v.w = acc[i][j4 * 4 + 3] * alpha;
            if (bias) {
                float4 bb = *(const float4*)(bias + c);
                v.x += bb.x; v.y += bb.y; v.z += bb.z; v.w += bb.w;
            }
            *(float4*)(C + (size_t)r * N + c) = v;
        }
    }
}

// ---------------------------------------------------------------------------
// Row softmax in place: 2048 elems/row, one block per row
// ---------------------------------------------------------------------------
__global__ __launch_bounds__(256) void softmax_kernel(float* __restrict__ attn)
{
    size_t row = blockIdx.x;
    float4* p = (float4*)attn + row * (TSEQ / 4);
    int tid = threadIdx.x;

    float4 a = p[tid];
    float4 b = p[tid + 256];

    float m = fmaxf(fmaxf(fmaxf(a.x, a.y), fmaxf(a.z, a.w)),
                    fmaxf(fmaxf(b.x, b.y), fmaxf(b.z, b.w)));
    #pragma unroll
    for (int o = 16; o > 0; o >>= 1) m = fmaxf(m, __shfl_xor_sync(0xffffffffu, m, o));

    __shared__ float ws[8];
    int w = tid >> 5, l = tid & 31;
    if (l == 0) ws[w] = m;
    __syncthreads();
    if (w == 0) {
        float s = (l < 8) ? ws[l] : -3.4e38f;
        #pragma unroll
        for (int o = 4; o > 0; o >>= 1) s = fmaxf(s, __shfl_xor_sync(0xffffffffu, s, o));
        if (l == 0) ws[0] = s;
    }
    __syncthreads();
    m = ws[0];
    __syncthreads();   // before reusing ws for the sum

    a.x = __expf(a.x - m); a.y = __expf(a.y - m);
    a.z = __expf(a.z - m); a.w = __expf(a.w - m);
    b.x = __expf(b.x - m); b.y = __expf(b.y - m);
    b.z = __expf(b.z - m); b.w = __expf(b.w - m);

    float ssum = a.x + a.y + a.z + a.w + b.x + b.y + b.z + b.w;
    #pragma unroll
    for (int o = 16; o > 0; o >>= 1) ssum += __shfl_xor_sync(0xffffffffu, ssum, o);
    if (l == 0) ws[w] = ssum;
    __syncthreads();
    if (w == 0) {
        float s = (l < 8) ? ws[l] : 0.0f;
        #pragma unroll
        for (int o = 4; o > 0; o >>= 1) s += __shfl_xor_sync(0xffffffffu, s, o);
        if (l == 0) ws[0] = s;
    }
    __syncthreads();
    float inv = 1.0f / ws[0];

    a.x *= inv; a.y *= inv; a.z *= inv; a.w *= inv;
    b.x *= inv; b.y *= inv; b.z *= inv; b.w *= inv;
    p[tid]       = a;
    p[tid + 256] = b;
}

// ---------------------------------------------------------------------------
// O = P[2048,2048] x V[2048,64], per group; scatter epilogue implements
// swapaxes(1,2).reshape(B,T,D):
//   out[g,s,e] -> b=g>>4, t=(g&15)*128 + 2e + (s>>10), d = s & 1023
// Tiles: BM=64, BN=64(full), BK=32; 256 threads, 4x4 per thread.
// ---------------------------------------------------------------------------
__global__ __launch_bounds__(256) void pv_kernel(
    const float* __restrict__ P, const float* __restrict__ V,
    float* __restrict__ Out)
{
    int g = blockIdx.z;
    int rowBase = blockIdx.y * 64;
    const float* Pg = P + (size_t)g * ATTN_PER_G;
    const float* Vg = V + (size_t)g * GRP_STRIDE;

    __shared__ float As[32][68];   // [k][m], padded (68*4B multiple of 16)
    __shared__ float Bs[32][64];   // [k][n]

    int tid = threadIdx.x;
    int ty = tid / 16, tx = tid % 16;

    float acc[4][4];
    #pragma unroll
    for (int i = 0; i < 4; i++)
        #pragma unroll
        for (int j = 0; j < 4; j++) acc[i][j] = 0.0f;

    int aRow = tid / 8;            // 0..31
    int aCol = (tid % 8) * 4;      // 0..28
    int bRow = tid / 16;           // 0..15
    int bCol = (tid % 16) * 4;     // 0..60

    for (int k0 = 0; k0 < TSEQ; k0 += 32) {
        #pragma unroll
        for (int p = 0; p < 2; p++) {
            int r = aRow + p * 32;
            float4 a = *(const float4*)(Pg + (size_t)(rowBase + r) * TSEQ + k0 + aCol);
            As[aCol + 0][r] = a.x;
            As[aCol + 1][r] = a.y;
            As[aCol + 2][r] = a.z;
            As[aCol + 3][r] = a.w;
        }
        #pragma unroll
        for (int p = 0; p < 2; p++) {
            int kr = bRow + p * 16;
            float4 b = *(const float4*)(Vg + (size_t)(k0 + kr) * DK + bCol);
            *(float4*)&Bs[kr][bCol] = b;
        }
        __syncthreads();

        #pragma unroll
        for (int kk = 0; kk < 32; kk++) {
            float4 af = *(const float4*)&As[kk][ty * 4];
            float4 bf = *(const float4*)&Bs[kk][tx * 4];
            float ra[4] = {af.x, af.y, af.z, af.w};
            float rb[4] = {bf.x, bf.y, bf.z, bf.w};
            #pragma unroll
            for (int i = 0; i < 4; i++)
                #pragma unroll
                for (int j = 0; j < 4; j++)
                    acc[i][j] = fmaf(ra[i], rb[j], acc[i][j]);
        }
        __syncthreads();
    }

    int b  = g >> 4;
    int gg = g & 15;
    #pragma unroll
    for (int i = 0; i < 4; i++) {
        int s   = rowBase + ty * 4 + i;
        int thi = s >> 10;
        int d   = s & 1023;
        #pragma unroll
        for (int j = 0; j < 4; j++) {
            int e = tx * 4 + j;
            int t = gg * 128 + 2 * e + thi;
            Out[(size_t)b * 2097152 + (size_t)t * 1024 + d] = acc[i][j];
        }
    }
}

// ---------------------------------------------------------------------------
// kernel_launch
// ---------------------------------------------------------------------------
extern "C" void kernel_launch(void* const* d_in, const int* in_sizes, int n_in,
                              void* d_out, int out_size)
{
    const float* x  = (const float*)d_in[0];
    const float* sc = (const float*)d_in[1];
    const float* wq = (const float*)d_in[2];
    const float* bq = (const float*)d_in[3];
    const float* wk = (const float*)d_in[4];
    const float* bk = (const float*)d_in[5];
    const float* wv = (const float*)d_in[6];
    const float* bv = (const float*)d_in[7];

    float* out  = (float*)d_out;          // [B,T,D] = 4194304 floats
    float* attn = out + OUT_ELEMS;        // [32,2048,2048]

    float *xn, *q, *k, *v;
    cudaGetSymbolAddress((void**)&xn, g_xn);
    cudaGetSymbolAddress((void**)&q,  g_q);
    cudaGetSymbolAddress((void**)&k,  g_k);
    cudaGetSymbolAddress((void**)&v,  g_v);

    // 1) xn = scale_norm(x)
    scalenorm_kernel<<<ROWS, 256>>>(x, xn, sc);

    // 2) projections: q/k/v = xn @ W^T + b
    dim3 gp(DMODEL / 128, ROWS / 128, 1);   // (8, 32)
    sgemm_nt<<<gp, 256>>>(xn, wq, bq, q, ROWS, DMODEL, DMODEL, 0, 0, 0, 1.0f);
    sgemm_nt<<<gp, 256>>>(xn, wk, bk, k, ROWS, DMODEL, DMODEL, 0, 0, 0, 1.0f);
    sgemm_nt<<<gp, 256>>>(xn, wv, bv, v, ROWS, DMODEL, DMODEL, 0, 0, 0, 1.0f);

    // 3) scale_norm over full D (in place)
    scalenorm_kernel<<<ROWS, 256>>>(q, q, sc);
    scalenorm_kernel<<<ROWS, 256>>>(k, k, sc);
    scalenorm_kernel<<<ROWS, 256>>>(v, v, sc);

    // 4) S = Q K^T / sqrt(dk), per group, written into d_out attn region
    dim3 gs(TSEQ / 128, TSEQ / 128, NGRP);  // (16, 16, 32)
    sgemm_nt<<<gs, 256>>>(q, k, nullptr, attn, TSEQ, TSEQ, DK,
                          GRP_STRIDE, GRP_STRIDE, ATTN_PER_G, 0.125f);

    // 5) row softmax in place
    softmax_kernel<<<NGRP * TSEQ, 256>>>(attn);

    // 6) O = attn @ V with scatter to output layout
    dim3 go(1, TSEQ / 64, NGRP);            // (1, 32, 32)
    pv_kernel<<<go, 256>>>(attn, v, out);
}

// round 3
// speedup vs baseline: 1.8983x; 1.8983x over previous
#include <cuda_runtime.h>
#include <cuda_bf16.h>
#include <math.h>
#include <stdint.h>

// Problem constants
#define ROWS   4096      // B*T
#define DMODEL 1024
#define TSEQ   2048
#define DK     64
#define NGRP   32        // B*H
#define OUT_ELEMS 4194304        // 2*2048*1024
#define ATTN_PER_G 4194304       // 2048*2048
#define GRP_STRIDE 131072        // T*dk

// Scratch (static __device__ — no allocation allowed)
__device__ float g_xn[ROWS * DMODEL];
__device__ float g_q [ROWS * DMODEL];
__device__ float g_k [ROWS * DMODEL];
__device__ float g_v [ROWS * DMODEL];
__device__ __nv_bfloat16 g_vh[NGRP * DK * TSEQ];   // V^T hi  [g][n=64][k=2048]
__device__ __nv_bfloat16 g_vl[NGRP * DK * TSEQ];   // V^T lo

// ===========================================================================
// helpers
// ===========================================================================
__device__ __forceinline__ uint32_t smem_u32(const void* p) {
    uint32_t a;
    asm("{ .reg .u64 t; cvta.to.shared.u64 t, %1; cvt.u32.u64 %0, t; }"
        : "=r"(a) : "l"(p));
    return a;
}

__device__ __forceinline__ void ldsm4(uint32_t* r, uint32_t addr) {
    asm volatile("ldmatrix.sync.aligned.m8n8.x4.shared.b16 {%0,%1,%2,%3}, [%4];"
                 : "=r"(r[0]), "=r"(r[1]), "=r"(r[2]), "=r"(r[3]) : "r"(addr));
}

__device__ __forceinline__ void mma16816(float* c, const uint32_t* a,
                                         const uint32_t* b) {
    asm volatile(
        "mma.sync.aligned.m16n8k16.row.col.f32.bf16.bf16.f32 "
        "{%0,%1,%2,%3}, {%4,%5,%6,%7}, {%8,%9}, {%0,%1,%2,%3};"
        : "+f"(c[0]), "+f"(c[1]), "+f"(c[2]), "+f"(c[3])
        : "r"(a[0]), "r"(a[1]), "r"(a[2]), "r"(a[3]), "r"(b[0]), "r"(b[1]));
}

// split fp32x4 -> bf16 hi (truncate) + bf16 lo (round(x - hi)); exact 2-term
__device__ __forceinline__ void split_f4(float4 v, uint2& hi, uint2& lo) {
    uint32_t u0 = __float_as_uint(v.x), u1 = __float_as_uint(v.y);
    uint32_t u2 = __float_as_uint(v.z), u3 = __float_as_uint(v.w);
    hi.x = (u0 >> 16) | (u1 & 0xFFFF0000u);
    hi.y = (u2 >> 16) | (u3 & 0xFFFF0000u);
    float l0 = v.x - __uint_as_float(u0 & 0xFFFF0000u);
    float l1 = v.y - __uint_as_float(u1 & 0xFFFF0000u);
    float l2 = v.z - __uint_as_float(u2 & 0xFFFF0000u);
    float l3 = v.w - __uint_as_float(u3 & 0xFFFF0000u);
    __nv_bfloat162 p01 = __floats2bfloat162_rn(l0, l1);
    __nv_bfloat162 p23 = __floats2bfloat162_rn(l2, l3);
    lo.x = *reinterpret_cast<uint32_t*>(&p01);
    lo.y = *reinterpret_cast<uint32_t*>(&p23);
}

// ===========================================================================
// scale_norm over a row of 1024
// ===========================================================================
__global__ __launch_bounds__(256) void scalenorm_kernel(
    const float* __restrict__ in, float* __restrict__ out,
    const float* __restrict__ scale_p)
{
    int row = blockIdx.x;
    int tid = threadIdx.x;
    const float4* rin  = (const float4*)in  + (size_t)row * (DMODEL / 4);
    float4*       rout = (float4*)out       + (size_t)row * (DMODEL / 4);

    float4 f = rin[tid];
    float ssq = f.x * f.x + f.y * f.y + f.z * f.z + f.w * f.w;
    #pragma unroll
    for (int o = 16; o > 0; o >>= 1) ssq += __shfl_xor_sync(0xffffffffu, ssq, o);

    __shared__ float ws[8];
    int w = tid >> 5, l = tid & 31;
    if (l == 0) ws[w] = ssq;
    __syncthreads();
    if (w == 0) {
        float s = (l < 8) ? ws[l] : 0.0f;
        #pragma unroll
        for (int o = 4; o > 0; o >>= 1) s += __shfl_xor_sync(0xffffffffu, s, o);
        if (l == 0) ws[0] = s;
    }
    __syncthreads();

    float n = sqrtf(ws[0]);
    float factor = scale_p[0] / fmaxf(n, 1e-5f);
    f.x *= factor; f.y *= factor; f.z *= factor; f.w *= factor;
    rout[tid] = f;
}

// ===========================================================================
// V^T + hi/lo split:  v[g][k=2048][n=64] fp32 -> vt hi/lo [g][n=64][k=2048]
// ===========================================================================
__global__ __launch_bounds__(256) void vt_convert(
    const float* __restrict__ v,
    __nv_bfloat16* __restrict__ vh, __nv_bfloat16* __restrict__ vl)
{
    int g  = blockIdx.z;
    int k0 = blockIdx.x * 64;
    const float* vg = v + (size_t)g * GRP_STRIDE;
    __shared__ float sm[64][68];

    int t  = threadIdx.x;
    int kr = t >> 2;
    int f4 = (t & 3) * 4;
    const float4* rp = (const float4*)(vg + (size_t)(k0 + kr) * DK);
    #pragma unroll
    for (int i = 0; i < 4; i++) {
        float4 f = rp[f4 + i];
        *(float4*)&sm[kr][(f4 + i) * 4] = f;
    }
    __syncthreads();

    int n = t >> 2;
    size_t obase = (size_t)g * (DK * TSEQ) + (size_t)n * TSEQ + k0;
    #pragma unroll
    for (int j = 0; j < 4; j++) {
        int kk = (t & 3) * 16 + j * 4;
        float4 f = make_float4(sm[kk + 0][n], sm[kk + 1][n],
                               sm[kk + 2][n], sm[kk + 3][n]);
        uint2 hi, lo;
        split_f4(f, hi, lo);
        *(uint2*)((char*)vh + (obase + kk) * 2) = hi;
        *(uint2*)((char*)vl + (obase + kk) * 2) = lo;
    }
}

// ===========================================================================
// GEMM NT via mma.sync bf16 2-term split.
// C = alpha*(A[M,K] @ B[N,K]^T) + bias[N].  Tiles: BM=128, BN=128, BK=32.
// 8 warps as 2(m) x 4(n); warp tile 64x32. smem rows padded to 80B
// (conflict-free for ldmatrix). Double-buffered LDG->convert->STS.
// ===========================================================================
#define GST 40960   // stage: Ah 10240 | Al 10240 | Bh 10240 | Bl 10240
#define GEMM_SMEM (2 * GST)

__device__ __forceinline__ void sts_gemm(char* s, const float4* ra,
                                         const float4* rb, int rowoff, int lc) {
    #pragma unroll
    for (int i = 0; i < 4; i++) {
        uint2 h, l;
        split_f4(ra[i], h, l);
        *(uint2*)(s +     0 + rowoff + (lc + 4 * i) * 2) = h;
        *(uint2*)(s + 10240 + rowoff + (lc + 4 * i) * 2) = l;
        split_f4(rb[i], h, l);
        *(uint2*)(s + 20480 + rowoff + (lc + 4 * i) * 2) = h;
        *(uint2*)(s + 30720 + rowoff + (lc + 4 * i) * 2) = l;
    }
}

__global__ __launch_bounds__(256, 1) void gemm_mma(
    const float* __restrict__ A, const float* __restrict__ B,
    const float* __restrict__ bias, float* __restrict__ C,
    int K, int lda, int ldb, int ldc,
    long sA, long sB, long sC, float alpha)
{
    extern __shared__ char smx[];
    uint32_t sbase = smem_u32(smx);

    A += (long)blockIdx.z * sA;
    B += (long)blockIdx.z * sB;
    C += (long)blockIdx.z * sC;
    int rowBase = blockIdx.y * 128;
    int colBase = blockIdx.x * 128;

    int tid = threadIdx.x, lane = tid & 31, wid = tid >> 5;
    int wm = wid >> 2, wn = wid & 3;
    int lr = tid >> 1, lc = (tid & 1) * 16;
    int rowoff = lr * 80;

    const float* Abase = A + (size_t)(rowBase + lr) * lda + lc;
    const float* Bbase = B + (size_t)(colBase + lr) * ldb + lc;

    float4 ra[4], rb[4];
    #pragma unroll
    for (int i = 0; i < 4; i++) {
        ra[i] = *(const float4*)(Abase + 4 * i);
        rb[i] = *(const float4*)(Bbase + 4 * i);
    }
    sts_gemm(smx, ra, rb, rowoff, lc);
    __syncthreads();

    float acc[4][4][4];
    #pragma unroll
    for (int a = 0; a < 4; a++)
        #pragma unroll
        for (int b = 0; b < 4; b++)
            #pragma unroll
            for (int r = 0; r < 4; r++) acc[a][b][r] = 0.0f;

    int NC = K >> 5;
    for (int c = 0; c < NC; c++) {
        if (c + 1 < NC) {
            const float* ap = Abase + (c + 1) * 32;
            const float* bp = Bbase + (c + 1) * 32;
            #pragma unroll
            for (int i = 0; i < 4; i++) {
                ra[i] = *(const float4*)(ap + 4 * i);
                rb[i] = *(const float4*)(bp + 4 * i);
            }
        }
        uint32_t s0 = sbase + (c & 1) * GST;
        #pragma unroll
        for (int kk = 0; kk < 2; kk++) {
            uint32_t ah[4][4], al[4][4];
            #pragma unroll
            for (int mt = 0; mt < 4; mt++) {
                int row = wm * 64 + mt * 16 + (lane & 15);
                uint32_t off = row * 80 + kk * 32 + (lane >> 4) * 16;
                ldsm4(ah[mt], s0 + off);
                ldsm4(al[mt], s0 + 10240 + off);
            }
            uint32_t bh[2][4], bl[2][4];
            #pragma unroll
            for (int np = 0; np < 2; np++) {
                int nrow = wn * 32 + np * 16 + ((lane >> 4) << 3) + (lane & 7);
                uint32_t off = nrow * 80 + kk * 32 + ((lane >> 3) & 1) * 16;
                ldsm4(bh[np], s0 + 20480 + off);
                ldsm4(bl[np], s0 + 30720 + off);
            }
            #pragma unroll
            for (int mt = 0; mt < 4; mt++)
                #pragma unroll
                for (int nt = 0; nt < 4; nt++) {
                    const uint32_t* ph = &bh[nt >> 1][(nt & 1) * 2];
                    const uint32_t* pl = &bl[nt >> 1][(nt & 1) * 2];
                    mma16816(acc[mt][nt], ah[mt], ph);
                    mma16816(acc[mt][nt], ah[mt], pl);
                    mma16816(acc[mt][nt], al[mt], ph);
                }
        }
        if (c + 1 < NC)
            sts_gemm(smx + ((c + 1) & 1) * GST, ra, rb, rowoff, lc);
        __syncthreads();
    }

    // epilogue
    int r0 = rowBase + wm * 64 + (lane >> 2);
    int c0 = colBase + wn * 32 + (lane & 3) * 2;
    #pragma unroll
    for (int nt = 0; nt < 4; nt++) {
        int col = c0 + nt * 8;
        float b0 = 0.0f, b1 = 0.0f;
        if (bias) { b0 = bias[col]; b1 = bias[col + 1]; }
        #pragma unroll
        for (int mt = 0; mt < 4; mt++) {
            int row = r0 + mt * 16;
            float2 v0 = make_float2(acc[mt][nt][0] * alpha + b0,
                                    acc[mt][nt][1] * alpha + b1);
            float2 v1 = make_float2(acc[mt][nt][2] * alpha + b0,
                                    acc[mt][nt][3] * alpha + b1);
            *(float2*)(C + (size_t)row * ldc + col) = v0;
            *(float2*)(C + (size_t)(row + 8) * ldc + col) = v1;
        }
    }
}

// ===========================================================================
// PV: O[g] = attn[g][2048,2048] @ V[g]^T-tiles (pre-split bf16), scatter
// epilogue for swapaxes(1,2).reshape.  BM=128, BN=64, BK=32.
// 8 warps as 4(m) x 2(n); warp tile 32x32.
// ===========================================================================
#define PST 30720   // Ah 10240 | Al 10240 | Bh 5120 | Bl 5120
#define PV_SMEM (2 * PST)

__global__ __launch_bounds__(256, 1) void pv_mma(
    const float* __restrict__ P,
    const __nv_bfloat16* __restrict__ vh, const __nv_bfloat16* __restrict__ vl,
    float* __restrict__ Out)
{
    extern __shared__ char smx[];
    uint32_t sbase = smem_u32(smx);

    int g = blockIdx.z;
    int rowBase = blockIdx.x * 128;
    const float* Pg = P + (size_t)g * ATTN_PER_G;
    const __nv_bfloat16* vhg = vh + (size_t)g * (DK * TSEQ);
    const __nv_bfloat16* vlg = vl + (size_t)g * (DK * TSEQ);

    int tid = threadIdx.x, lane = tid & 31, wid = tid >> 5;
    int wm = wid >> 1, wn = wid & 1;
    int lr = tid >> 1, lc = (tid & 1) * 16;
    int rowoff = lr * 80;

    const float* Abase = Pg + (size_t)(rowBase + lr) * TSEQ + lc;
    int bn = tid >> 2, bch = tid & 3;
    const __nv_bfloat16* BhBase = vhg + (size_t)bn * TSEQ + bch * 8;
    const __nv_bfloat16* BlBase = vlg + (size_t)bn * TSEQ + bch * 8;
    int boff = bn * 80 + bch * 16;

    float4 ra[4];
    uint4 rbh, rbl;
    #pragma unroll
    for (int i = 0; i < 4; i++) ra[i] = *(const float4*)(Abase + 4 * i);
    rbh = *(const uint4*)BhBase;
    rbl = *(const uint4*)BlBase;
    {
        char* s = smx;
        #pragma unroll
        for (int i = 0; i < 4; i++) {
            uint2 h, l;
            split_f4(ra[i], h, l);
            *(uint2*)(s +     0 + rowoff + (lc + 4 * i) * 2) = h;
            *(uint2*)(s + 10240 + rowoff + (lc + 4 * i) * 2) = l;
        }
        *(uint4*)(s + 20480 + boff) = rbh;
        *(uint4*)(s + 25600 + boff) = rbl;
    }
    __syncthreads();

    float acc[2][4][4];
    #pragma unroll
    for (int a = 0; a < 2; a++)
        #pragma unroll
        for (int b = 0; b < 4; b++)
            #pragma unroll
            for (int r = 0; r < 4; r++) acc[a][b][r] = 0.0f;

    const int NC = TSEQ / 32;   // 64
    for (int c = 0; c < NC; c++) {
        if (c + 1 < NC) {
            const float* ap = Abase + (c + 1) * 32;
            #pragma unroll
            for (int i = 0; i < 4; i++) ra[i] = *(const float4*)(ap + 4 * i);
            rbh = *(const uint4*)(BhBase + (c + 1) * 32);
            rbl = *(const uint4*)(BlBase + (c + 1) * 32);
        }
        uint32_t s0 = sbase + (c & 1) * PST;
        #pragma unroll
        for (int kk = 0; kk < 2; kk++) {
            uint32_t ah[2][4], al[2][4];
            #pragma unroll
            for (int mt = 0; mt < 2; mt++) {
                int row = wm * 32 + mt * 16 + (lane & 15);
                uint32_t off = row * 80 + kk * 32 + (lane >> 4) * 16;
                ldsm4(ah[mt], s0 + off);
                ldsm4(al[mt], s0 + 10240 + off);
            }
            uint32_t bh[2][4], bl[2][4];
            #pragma unroll
            for (int np = 0; np < 2; np++) {
                int nrow = wn * 32 + np * 16 + ((lane >> 4) << 3) + (lane & 7);
                uint32_t off = nrow * 80 + kk * 32 + ((lane >> 3) & 1) * 16;
                ldsm4(bh[np], s0 + 20480 + off);
                ldsm4(bl[np], s0 + 25600 + off);
            }
            #pragma unroll
            for (int mt = 0; mt < 2; mt++)
                #pragma unroll
                for (int nt = 0; nt < 4; nt++) {
                    const uint32_t* ph = &bh[nt >> 1][(nt & 1) * 2];
                    const uint32_t* pl = &bl[nt >> 1][(nt & 1) * 2];
                    mma16816(acc[mt][nt], ah[mt], ph);
                    mma16816(acc[mt][nt], ah[mt], pl);
                    mma16816(acc[mt][nt], al[mt], ph);
                }
        }
        if (c + 1 < NC) {
            char* s = smx + ((c + 1) & 1) * PST;
            #pragma unroll
            for (int i = 0; i < 4; i++) {
                uint2 h, l;
                split_f4(ra[i], h, l);
                *(uint2*)(s +     0 + rowoff + (lc + 4 * i) * 2) = h;
                *(uint2*)(s + 10240 + rowoff + (lc + 4 * i) * 2) = l;
            }
            *(uint4*)(s + 20480 + boff) = rbh;
            *(uint4*)(s + 25600 + boff) = rbl;
        }
        __syncthreads();
    }

    // scatter epilogue: out[g, s, e] -> b=g>>4, t=(g&15)*128 + 2e + (s>>10), d=s&1023
    int b  = g >> 4;
    int gg = g & 15;
    float* ob = Out + (size_t)b * 2097152;
    int rr = rowBase + wm * 32 + (lane >> 2);
    int e0 = wn * 32 + (lane & 3) * 2;
    #pragma unroll
    for (int mt = 0; mt < 2; mt++) {
        #pragma unroll
        for (int half = 0; half < 2; half++) {
            int s   = rr + mt * 16 + half * 8;
            int thi = s >> 10;
            int d   = s & 1023;
            #pragma unroll
            for (int nt = 0; nt < 4; nt++) {
                int e  = e0 + nt * 8;
                int t0 = gg * 128 + 2 * e + thi;
                int t1 = gg * 128 + 2 * (e + 1) + thi;
                ob[(size_t)t0 * 1024 + d] = acc[mt][nt][half * 2 + 0];
                ob[(size_t)t1 * 1024 + d] = acc[mt][nt][half * 2 + 1];
            }
        }
    }
}

// ===========================================================================
// Row softmax in place: 2048 elems/row
// ===========================================================================
__global__ __launch_bounds__(256) void softmax_kernel(float* __restrict__ attn)
{
    size_t row = blockIdx.x;
    float4* p = (float4*)attn + row * (TSEQ / 4);
    int tid = threadIdx.x;

    float4 a = p[tid];
    float4 b = p[tid + 256];

    float m = fmaxf(fmaxf(fmaxf(a.x, a.y), fmaxf(a.z, a.w)),
                    fmaxf(fmaxf(b.x, b.y), fmaxf(b.z, b.w)));
    #pragma unroll
    for (int o = 16; o > 0; o >>= 1) m = fmaxf(m, __shfl_xor_sync(0xffffffffu, m, o));

    __shared__ float ws[8];
    int w = tid >> 5, l = tid & 31;
    if (l == 0) ws[w] = m;
    __syncthreads();
    if (w == 0) {
        float s = (l < 8) ? ws[l] : -3.4e38f;
        #pragma unroll
        for (int o = 4; o > 0; o >>= 1) s = fmaxf(s, __shfl_xor_sync(0xffffffffu, s, o));
        if (l == 0) ws[0] = s;
    }
    __syncthreads();
    m = ws[0];
    __syncthreads();

    a.x = __expf(a.x - m); a.y = __expf(a.y - m);
    a.z = __expf(a.z - m); a.w = __expf(a.w - m);
    b.x = __expf(b.x - m); b.y = __expf(b.y - m);
    b.z = __expf(b.z - m); b.w = __expf(b.w - m);

    float ssum = a.x + a.y + a.z + a.w + b.x + b.y + b.z + b.w;
    #pragma unroll
    for (int o = 16; o > 0; o >>= 1) ssum += __shfl_xor_sync(0xffffffffu, ssum, o);
    if (l == 0) ws[w] = ssum;
    __syncthreads();
    if (w == 0) {
        float s = (l < 8) ? ws[l] : 0.0f;
        #pragma unroll
        for (int o = 4; o > 0; o >>= 1) s += __shfl_xor_sync(0xffffffffu, s, o);
        if (l == 0) ws[0] = s;
    }
    __syncthreads();
    float inv = 1.0f / ws[0];

    a.x *= inv; a.y *= inv; a.z *= inv; a.w *= inv;
    b.x *= inv; b.y *= inv; b.z *= inv; b.w *= inv;
    p[tid]       = a;
    p[tid + 256] = b;
}

// ===========================================================================
// kernel_launch
// ===========================================================================
extern "C" void kernel_launch(void* const* d_in, const int* in_sizes, int n_in,
                              void* d_out, int out_size)
{
    const float* x  = (const float*)d_in[0];
    const float* sc = (const float*)d_in[1];
    const float* wq = (const float*)d_in[2];
    const float* bq = (const float*)d_in[3];
    const float* wk = (const float*)d_in[4];
    const float* bk = (const float*)d_in[5];
    const float* wv = (const float*)d_in[6];
    const float* bv = (const float*)d_in[7];

    float* out  = (float*)d_out;
    float* attn = out + OUT_ELEMS;

    float *xn, *q, *k, *v;
    __nv_bfloat16 *vh, *vl;
    cudaGetSymbolAddress((void**)&xn, g_xn);
    cudaGetSymbolAddress((void**)&q,  g_q);
    cudaGetSymbolAddress((void**)&k,  g_k);
    cudaGetSymbolAddress((void**)&v,  g_v);
    cudaGetSymbolAddress((void**)&vh, g_vh);
    cudaGetSymbolAddress((void**)&vl, g_vl);

    cudaFuncSetAttribute(gemm_mma, cudaFuncAttributeMaxDynamicSharedMemorySize, GEMM_SMEM);
    cudaFuncSetAttribute(pv_mma,   cudaFuncAttributeMaxDynamicSharedMemorySize, PV_SMEM);

    // 1) xn = scale_norm(x)
    scalenorm_kernel<<<ROWS, 256>>>(x, xn, sc);

    // 2) projections q/k/v = xn @ W^T + b   (tensor cores, split-bf16)
    dim3 gp(DMODEL / 128, ROWS / 128, 1);   // (8, 32)
    gemm_mma<<<gp, 256, GEMM_SMEM>>>(xn, wq, bq, q, DMODEL, DMODEL, DMODEL, DMODEL, 0, 0, 0, 1.0f);
    gemm_mma<<<gp, 256, GEMM_SMEM>>>(xn, wk, bk, k, DMODEL, DMODEL, DMODEL, DMODEL, 0, 0, 0, 1.0f);
    gemm_mma<<<gp, 256, GEMM_SMEM>>>(xn, wv, bv, v, DMODEL, DMODEL, DMODEL, DMODEL, 0, 0, 0, 1.0f);

    // 3) scale_norm over full D (in place)
    scalenorm_kernel<<<ROWS, 256>>>(q, q, sc);
    scalenorm_kernel<<<ROWS, 256>>>(k, k, sc);
    scalenorm_kernel<<<ROWS, 256>>>(v, v, sc);

    // 3b) V^T hi/lo split
    vt_convert<<<dim3(TSEQ / 64, 1, NGRP), 256>>>(v, vh, vl);

    // 4) S = Q K^T / 8 into attn region (batched over 32 groups)
    dim3 gs(TSEQ / 128, TSEQ / 128, NGRP);  // (16, 16, 32)
    gemm_mma<<<gs, 256, GEMM_SMEM>>>(q, k, nullptr, attn, DK, DK, DK, TSEQ,
                                     GRP_STRIDE, GRP_STRIDE, ATTN_PER_G, 0.125f);

    // 5) softmax in place
    softmax_kernel<<<NGRP * TSEQ, 256>>>(attn);

    // 6) O = attn @ V with scatter epilogue
    pv_mma<<<dim3(TSEQ / 128, 1, NGRP), 256, PV_SMEM>>>(attn, vh, vl, out);
}

// round 4
// speedup vs baseline: 1.8989x; 1.0003x over previous
#include <cuda_runtime.h>
#include <cuda_bf16.h>
#include <math.h>
#include <stdint.h>

// Problem constants
#define ROWS   4096      // B*T
#define DMODEL 1024
#define TSEQ   2048
#define DK     64
#define NGRP   32        // B*H
#define OUT_ELEMS 4194304        // 2*2048*1024
#define ATTN_PER_G 4194304       // 2048*2048
#define GRP_STRIDE 131072        // T*dk

// Scratch (static __device__ — no allocation allowed)
__device__ float g_xn[ROWS * DMODEL];
__device__ float g_q [ROWS * DMODEL];
__device__ float g_k [ROWS * DMODEL];
__device__ float g_v [ROWS * DMODEL];
__device__ __nv_bfloat16 g_vh[NGRP * DK * TSEQ];   // V^T hi  [g][n=64][k=2048]
__device__ __nv_bfloat16 g_vl[NGRP * DK * TSEQ];   // V^T lo

// ===========================================================================
// helpers
// ===========================================================================
__device__ __forceinline__ uint32_t smem_u32(const void* p) {
    uint32_t a;
    asm("{ .reg .u64 t; cvta.to.shared.u64 t, %1; cvt.u32.u64 %0, t; }"
        : "=r"(a) : "l"(p));
    return a;
}

__device__ __forceinline__ void ldsm4(uint32_t* r, uint32_t addr) {
    asm volatile("ldmatrix.sync.aligned.m8n8.x4.shared.b16 {%0,%1,%2,%3}, [%4];"
                 : "=r"(r[0]), "=r"(r[1]), "=r"(r[2]), "=r"(r[3]) : "r"(addr));
}

__device__ __forceinline__ void mma16816(float* c, const uint32_t* a,
                                         const uint32_t* b) {
    asm volatile(
        "mma.sync.aligned.m16n8k16.row.col.f32.bf16.bf16.f32 "
        "{%0,%1,%2,%3}, {%4,%5,%6,%7}, {%8,%9}, {%0,%1,%2,%3};"
        : "+f"(c[0]), "+f"(c[1]), "+f"(c[2]), "+f"(c[3])
        : "r"(a[0]), "r"(a[1]), "r"(a[2]), "r"(a[3]), "r"(b[0]), "r"(b[1]));
}

// split fp32x4 -> bf16 hi (truncate) + bf16 lo (round(x - hi)); exact 2-term
__device__ __forceinline__ void split_f4(float4 v, uint2& hi, uint2& lo) {
    uint32_t u0 = __float_as_uint(v.x), u1 = __float_as_uint(v.y);
    uint32_t u2 = __float_as_uint(v.z), u3 = __float_as_uint(v.w);
    hi.x = (u0 >> 16) | (u1 & 0xFFFF0000u);
    hi.y = (u2 >> 16) | (u3 & 0xFFFF0000u);
    float l0 = v.x - __uint_as_float(u0 & 0xFFFF0000u);
    float l1 = v.y - __uint_as_float(u1 & 0xFFFF0000u);
    float l2 = v.z - __uint_as_float(u2 & 0xFFFF0000u);
    float l3 = v.w - __uint_as_float(u3 & 0xFFFF0000u);
    __nv_bfloat162 p01 = __floats2bfloat162_rn(l0, l1);
    __nv_bfloat162 p23 = __floats2bfloat162_rn(l2, l3);
    lo.x = *reinterpret_cast<uint32_t*>(&p01);
    lo.y = *reinterpret_cast<uint32_t*>(&p23);
}

// ===========================================================================
// scale_norm over a row of 1024
// ===========================================================================
__global__ __launch_bounds__(256) void scalenorm_kernel(
    const float* __restrict__ in, float* __restrict__ out,
    const float* __restrict__ scale_p)
{
    int row = blockIdx.x;
    int tid = threadIdx.x;
    const float4* rin  = (const float4*)in  + (size_t)row * (DMODEL / 4);
    float4*       rout = (float4*)out       + (size_t)row * (DMODEL / 4);

    float4 f = rin[tid];
    float ssq = f.x * f.x + f.y * f.y + f.z * f.z + f.w * f.w;
    #pragma unroll
    for (int o = 16; o > 0; o >>= 1) ssq += __shfl_xor_sync(0xffffffffu, ssq, o);

    __shared__ float ws[8];
    int w = tid >> 5, l = tid & 31;
    if (l == 0) ws[w] = ssq;
    __syncthreads();
    if (w == 0) {
        float s = (l < 8) ? ws[l] : 0.0f;
        #pragma unroll
        for (int o = 4; o > 0; o >>= 1) s += __shfl_xor_sync(0xffffffffu, s, o);
        if (l == 0) ws[0] = s;
    }
    __syncthreads();

    float n = sqrtf(ws[0]);
    float factor = scale_p[0] / fmaxf(n, 1e-5f);
    f.x *= factor; f.y *= factor; f.z *= factor; f.w *= factor;
    rout[tid] = f;
}

// ===========================================================================
// V^T + hi/lo split:  v[g][k=2048][n=64] fp32 -> vt hi/lo [g][n=64][k=2048]
// ===========================================================================
__global__ __launch_bounds__(256) void vt_convert(
    const float* __restrict__ v,
    __nv_bfloat16* __restrict__ vh, __nv_bfloat16* __restrict__ vl)
{
    int g  = blockIdx.z;
    int k0 = blockIdx.x * 64;
    const float* vg = v + (size_t)g * GRP_STRIDE;
    __shared__ float sm[64][68];

    int t  = threadIdx.x;
    int kr = t >> 2;
    int f4 = (t & 3) * 4;
    const float4* rp = (const float4*)(vg + (size_t)(k0 + kr) * DK);
    #pragma unroll
    for (int i = 0; i < 4; i++) {
        float4 f = rp[f4 + i];
        *(float4*)&sm[kr][(f4 + i) * 4] = f;
    }
    __syncthreads();

    int n = t >> 2;
    size_t obase = (size_t)g * (DK * TSEQ) + (size_t)n * TSEQ + k0;
    #pragma unroll
    for (int j = 0; j < 4; j++) {
        int kk = (t & 3) * 16 + j * 4;
        float4 f = make_float4(sm[kk + 0][n], sm[kk + 1][n],
                               sm[kk + 2][n], sm[kk + 3][n]);
        uint2 hi, lo;
        split_f4(f, hi, lo);
        *(uint2*)((char*)vh + (obase + kk) * 2) = hi;
        *(uint2*)((char*)vl + (obase + kk) * 2) = lo;
    }
}

// ===========================================================================
// GEMM NT via mma.sync bf16 2-term split.
// C = alpha*(A[M,K] @ B[N,K]^T) + bias[N].  Tiles: BM=128, BN=128, BK=32.
// 8 warps as 2(m) x 4(n); warp tile 64x32. smem rows padded to 80B
// (conflict-free for ldmatrix). Double-buffered LDG->convert->STS.
// ===========================================================================
#define GST 40960   // stage: Ah 10240 | Al 10240 | Bh 10240 | Bl 10240
#define GEMM_SMEM (2 * GST)

__device__ __forceinline__ void sts_gemm(char* s, const float4* ra,
                                         const float4* rb, int rowoff, int lc) {
    #pragma unroll
    for (int i = 0; i < 4; i++) {
        uint2 h, l;
        split_f4(ra[i], h, l);
        *(uint2*)(s +     0 + rowoff + (lc + 4 * i) * 2) = h;
        *(uint2*)(s + 10240 + rowoff + (lc + 4 * i) * 2) = l;
        split_f4(rb[i], h, l);
        *(uint2*)(s + 20480 + rowoff + (lc + 4 * i) * 2) = h;
        *(uint2*)(s + 30720 + rowoff + (lc + 4 * i) * 2) = l;
    }
}

__global__ __launch_bounds__(256, 1) void gemm_mma(
    const float* __restrict__ A, const float* __restrict__ B,
    const float* __restrict__ bias, float* __restrict__ C,
    int K, int lda, int ldb, int ldc,
    long sA, long sB, long sC, float alpha)
{
    extern __shared__ char smx[];
    uint32_t sbase = smem_u32(smx);

    A += (long)blockIdx.z * sA;
    B += (long)blockIdx.z * sB;
    C += (long)blockIdx.z * sC;
    int rowBase = blockIdx.y * 128;
    int colBase = blockIdx.x * 128;

    int tid = threadIdx.x, lane = tid & 31, wid = tid >> 5;
    int wm = wid >> 2, wn = wid & 3;
    int lr = tid >> 1, lc = (tid & 1) * 16;
    int rowoff = lr * 80;

    const float* Abase = A + (size_t)(rowBase + lr) * lda + lc;
    const float* Bbase = B + (size_t)(colBase + lr) * ldb + lc;

    float4 ra[4], rb[4];
    #pragma unroll
    for (int i = 0; i < 4; i++) {
        ra[i] = *(const float4*)(Abase + 4 * i);
        rb[i] = *(const float4*)(Bbase + 4 * i);
    }
    sts_gemm(smx, ra, rb, rowoff, lc);
    __syncthreads();

    float acc[4][4][4];
    #pragma unroll
    for (int a = 0; a < 4; a++)
        #pragma unroll
        for (int b = 0; b < 4; b++)
            #pragma unroll
            for (int r = 0; r < 4; r++) acc[a][b][r] = 0.0f;

    int NC = K >> 5;
    for (int c = 0; c < NC; c++) {
        if (c + 1 < NC) {
            const float* ap = Abase + (c + 1) * 32;
            const float* bp = Bbase + (c + 1) * 32;
            #pragma unroll
            for (int i = 0; i < 4; i++) {
                ra[i] = *(const float4*)(ap + 4 * i);
                rb[i] = *(const float4*)(bp + 4 * i);
            }
        }
        uint32_t s0 = sbase + (c & 1) * GST;
        #pragma unroll
        for (int kk = 0; kk < 2; kk++) {
            uint32_t ah[4][4], al[4][4];
            #pragma unroll
            for (int mt = 0; mt < 4; mt++) {
                int row = wm * 64 + mt * 16 + (lane & 15);
                uint32_t off = row * 80 + kk * 32 + (lane >> 4) * 16;
                ldsm4(ah[mt], s0 + off);
                ldsm4(al[mt], s0 + 10240 + off);
            }
            uint32_t bh[2][4], bl[2][4];
            #pragma unroll
            for (int np = 0; np < 2; np++) {
                int nrow = wn * 32 + np * 16 + ((lane >> 4) << 3) + (lane & 7);
                uint32_t off = nrow * 80 + kk * 32 + ((lane >> 3) & 1) * 16;
                ldsm4(bh[np], s0 + 20480 + off);
                ldsm4(bl[np], s0 + 30720 + off);
            }
            #pragma unroll
            for (int mt = 0; mt < 4; mt++)
                #pragma unroll
                for (int nt = 0; nt < 4; nt++) {
                    const uint32_t* ph = &bh[nt >> 1][(nt & 1) * 2];
                    const uint32_t* pl = &bl[nt >> 1][(nt & 1) * 2];
                    mma16816(acc[mt][nt], ah[mt], ph);
                    mma16816(acc[mt][nt], ah[mt], pl);
                    mma16816(acc[mt][nt], al[mt], ph);
                }
        }
        if (c + 1 < NC)
            sts_gemm(smx + ((c + 1) & 1) * GST, ra, rb, rowoff, lc);
        __syncthreads();
    }

    // epilogue
    int r0 = rowBase + wm * 64 + (lane >> 2);
    int c0 = colBase + wn * 32 + (lane & 3) * 2;
    #pragma unroll
    for (int nt = 0; nt < 4; nt++) {
        int col = c0 + nt * 8;
        float b0 = 0.0f, b1 = 0.0f;
        if (bias) { b0 = bias[col]; b1 = bias[col + 1]; }
        #pragma unroll
        for (int mt = 0; mt < 4; mt++) {
            int row = r0 + mt * 16;
            float2 v0 = make_float2(acc[mt][nt][0] * alpha + b0,
                                    acc[mt][nt][1] * alpha + b1);
            float2 v1 = make_float2(acc[mt][nt][2] * alpha + b0,
                                    acc[mt][nt][3] * alpha + b1);
            *(float2*)(C + (size_t)row * ldc + col) = v0;
            *(float2*)(C + (size_t)(row + 8) * ldc + col) = v1;
        }
    }
}

// ===========================================================================
// PV: O[g] = attn[g][2048,2048] @ V[g]^T-tiles (pre-split bf16), scatter
// epilogue for swapaxes(1,2).reshape.  BM=128, BN=64, BK=32.
// 8 warps as 4(m) x 2(n); warp tile 32x32.
// ===========================================================================
#define PST 30720   // Ah 10240 | Al 10240 | Bh 5120 | Bl 5120
#define PV_SMEM (2 * PST)

__global__ __launch_bounds__(256, 1) void pv_mma(
    const float* __restrict__ P,
    const __nv_bfloat16* __restrict__ vh, const __nv_bfloat16* __restrict__ vl,
    float* __restrict__ Out)
{
    extern __shared__ char smx[];
    uint32_t sbase = smem_u32(smx);

    int g = blockIdx.z;
    int rowBase = blockIdx.x * 128;
    const float* Pg = P + (size_t)g * ATTN_PER_G;
    const __nv_bfloat16* vhg = vh + (size_t)g * (DK * TSEQ);
    const __nv_bfloat16* vlg = vl + (size_t)g * (DK * TSEQ);

    int tid = threadIdx.x, lane = tid & 31, wid = tid >> 5;
    int wm = wid >> 1, wn = wid & 1;
    int lr = tid >> 1, lc = (tid & 1) * 16;
    int rowoff = lr * 80;

    const float* Abase = Pg + (size_t)(rowBase + lr) * TSEQ + lc;
    int bn = tid >> 2, bch = tid & 3;
    const __nv_bfloat16* BhBase = vhg + (size_t)bn * TSEQ + bch * 8;
    const __nv_bfloat16* BlBase = vlg + (size_t)bn * TSEQ + bch * 8;
    int boff = bn * 80 + bch * 16;

    float4 ra[4];
    uint4 rbh, rbl;
    #pragma unroll
    for (int i = 0; i < 4; i++) ra[i] = *(const float4*)(Abase + 4 * i);
    rbh = *(const uint4*)BhBase;
    rbl = *(const uint4*)BlBase;
    {
        char* s = smx;
        #pragma unroll
        for (int i = 0; i < 4; i++) {
            uint2 h, l;
            split_f4(ra[i], h, l);
            *(uint2*)(s +     0 + rowoff + (lc + 4 * i) * 2) = h;
            *(uint2*)(s + 10240 + rowoff + (lc + 4 * i) * 2) = l;
        }
        *(uint4*)(s + 20480 + boff) = rbh;
        *(uint4*)(s + 25600 + boff) = rbl;
    }
    __syncthreads();

    float acc[2][4][4];
    #pragma unroll
    for (int a = 0; a < 2; a++)
        #pragma unroll
        for (int b = 0; b < 4; b++)
            #pragma unroll
            for (int r = 0; r < 4; r++) acc[a][b][r] = 0.0f;

    const int NC = TSEQ / 32;   // 64
    for (int c = 0; c < NC; c++) {
        if (c + 1 < NC) {
            const float* ap = Abase + (c + 1) * 32;
            #pragma unroll
            for (int i = 0; i < 4; i++) ra[i] = *(const float4*)(ap + 4 * i);
            rbh = *(const uint4*)(BhBase + (c + 1) * 32);
            rbl = *(const uint4*)(BlBase + (c + 1) * 32);
        }
        uint32_t s0 = sbase + (c & 1) * PST;
        #pragma unroll
        for (int kk = 0; kk < 2; kk++) {
            uint32_t ah[2][4], al[2][4];
            #pragma unroll
            for (int mt = 0; mt < 2; mt++) {
                int row = wm * 32 + mt * 16 + (lane & 15);
                uint32_t off = row * 80 + kk * 32 + (lane >> 4) * 16;
                ldsm4(ah[mt], s0 + off);
                ldsm4(al[mt], s0 + 10240 + off);
            }
            uint32_t bh[2][4], bl[2][4];
            #pragma unroll
            for (int np = 0; np < 2; np++) {
                int nrow = wn * 32 + np * 16 + ((lane >> 4) << 3) + (lane & 7);
                uint32_t off = nrow * 80 + kk * 32 + ((lane >> 3) & 1) * 16;
                ldsm4(bh[np], s0 + 20480 + off);
                ldsm4(bl[np], s0 + 25600 + off);
            }
            #pragma unroll
            for (int mt = 0; mt < 2; mt++)
                #pragma unroll
                for (int nt = 0; nt < 4; nt++) {
                    const uint32_t* ph = &bh[nt >> 1][(nt & 1) * 2];
                    const uint32_t* pl = &bl[nt >> 1][(nt & 1) * 2];
                    mma16816(acc[mt][nt], ah[mt], ph);
                    mma16816(acc[mt][nt], ah[mt], pl);
                    mma16816(acc[mt][nt], al[mt], ph);
                }
        }
        if (c + 1 < NC) {
            char* s = smx + ((c + 1) & 1) * PST;
            #pragma unroll
            for (int i = 0; i < 4; i++) {
                uint2 h, l;
                split_f4(ra[i], h, l);
                *(uint2*)(s +     0 + rowoff + (lc + 4 * i) * 2) = h;
                *(uint2*)(s + 10240 + rowoff + (lc + 4 * i) * 2) = l;
            }
            *(uint4*)(s + 20480 + boff) = rbh;
            *(uint4*)(s + 25600 + boff) = rbl;
        }
        __syncthreads();
    }

    // scatter epilogue: out[g, s, e] -> b=g>>4, t=(g&15)*128 + 2e + (s>>10), d=s&1023
    int b  = g >> 4;
    int gg = g & 15;
    float* ob = Out + (size_t)b * 2097152;
    int rr = rowBase + wm * 32 + (lane >> 2);
    int e0 = wn * 32 + (lane & 3) * 2;
    #pragma unroll
    for (int mt = 0; mt < 2; mt++) {
        #pragma unroll
        for (int half = 0; half < 2; half++) {
            int s   = rr + mt * 16 + half * 8;
            int thi = s >> 10;
            int d   = s & 1023;
            #pragma unroll
            for (int nt = 0; nt < 4; nt++) {
                int e  = e0 + nt * 8;
                int t0 = gg * 128 + 2 * e + thi;
                int t1 = gg * 128 + 2 * (e + 1) + thi;
                ob[(size_t)t0 * 1024 + d] = acc[mt][nt][half * 2 + 0];
                ob[(size_t)t1 * 1024 + d] = acc[mt][nt][half * 2 + 1];
            }
        }
    }
}

// ===========================================================================
// Row softmax in place: 2048 elems/row
// ===========================================================================
__global__ __launch_bounds__(256) void softmax_kernel(float* __restrict__ attn)
{
    size_t row = blockIdx.x;
    float4* p = (float4*)attn + row * (TSEQ / 4);
    int tid = threadIdx.x;

    float4 a = p[tid];
    float4 b = p[tid + 256];

    float m = fmaxf(fmaxf(fmaxf(a.x, a.y), fmaxf(a.z, a.w)),
                    fmaxf(fmaxf(b.x, b.y), fmaxf(b.z, b.w)));
    #pragma unroll
    for (int o = 16; o > 0; o >>= 1) m = fmaxf(m, __shfl_xor_sync(0xffffffffu, m, o));

    __shared__ float ws[8];
    int w = tid >> 5, l = tid & 31;
    if (l == 0) ws[w] = m;
    __syncthreads();
    if (w == 0) {
        float s = (l < 8) ? ws[l] : -3.4e38f;
        #pragma unroll
        for (int o = 4; o > 0; o >>= 1) s = fmaxf(s, __shfl_xor_sync(0xffffffffu, s, o));
        if (l == 0) ws[0] = s;
    }
    __syncthreads();
    m = ws[0];
    __syncthreads();

    a.x = __expf(a.x - m); a.y = __expf(a.y - m);
    a.z = __expf(a.z - m); a.w = __expf(a.w - m);
    b.x = __expf(b.x - m); b.y = __expf(b.y - m);
    b.z = __expf(b.z - m); b.w = __expf(b.w - m);

    float ssum = a.x + a.y + a.z + a.w + b.x + b.y + b.z + b.w;
    #pragma unroll
    for (int o = 16; o > 0; o >>= 1) ssum += __shfl_xor_sync(0xffffffffu, ssum, o);
    if (l == 0) ws[w] = ssum;
    __syncthreads();
    if (w == 0) {
        float s = (l < 8) ? ws[l] : 0.0f;
        #pragma unroll
        for (int o = 4; o > 0; o >>= 1) s += __shfl_xor_sync(0xffffffffu, s, o);
        if (l == 0) ws[0] = s;
    }
    __syncthreads();
    float inv = 1.0f / ws[0];

    a.x *= inv; a.y *= inv; a.z *= inv; a.w *= inv;
    b.x *= inv; b.y *= inv; b.z *= inv; b.w *= inv;
    p[tid]       = a;
    p[tid + 256] = b;
}

// ===========================================================================
// kernel_launch
// ===========================================================================
extern "C" void kernel_launch(void* const* d_in, const int* in_sizes, int n_in,
                              void* d_out, int out_size)
{
    const float* x  = (const float*)d_in[0];
    const float* sc = (const float*)d_in[1];
    const float* wq = (const float*)d_in[2];
    const float* bq = (const float*)d_in[3];
    const float* wk = (const float*)d_in[4];
    const float* bk = (const float*)d_in[5];
    const float* wv = (const float*)d_in[6];
    const float* bv = (const float*)d_in[7];

    float* out  = (float*)d_out;
    float* attn = out + OUT_ELEMS;

    float *xn, *q, *k, *v;
    __nv_bfloat16 *vh, *vl;
    cudaGetSymbolAddress((void**)&xn, g_xn);
    cudaGetSymbolAddress((void**)&q,  g_q);
    cudaGetSymbolAddress((void**)&k,  g_k);
    cudaGetSymbolAddress((void**)&v,  g_v);
    cudaGetSymbolAddress((void**)&vh, g_vh);
    cudaGetSymbolAddress((void**)&vl, g_vl);

    cudaFuncSetAttribute(gemm_mma, cudaFuncAttributeMaxDynamicSharedMemorySize, GEMM_SMEM);
    cudaFuncSetAttribute(pv_mma,   cudaFuncAttributeMaxDynamicSharedMemorySize, PV_SMEM);

    // 1) xn = scale_norm(x)
    scalenorm_kernel<<<ROWS, 256>>>(x, xn, sc);

    // 2) projections q/k/v = xn @ W^T + b   (tensor cores, split-bf16)
    dim3 gp(DMODEL / 128, ROWS / 128, 1);   // (8, 32)
    gemm_mma<<<gp, 256, GEMM_SMEM>>>(xn, wq, bq, q, DMODEL, DMODEL, DMODEL, DMODEL, 0, 0, 0, 1.0f);
    gemm_mma<<<gp, 256, GEMM_SMEM>>>(xn, wk, bk, k, DMODEL, DMODEL, DMODEL, DMODEL, 0, 0, 0, 1.0f);
    gemm_mma<<<gp, 256, GEMM_SMEM>>>(xn, wv, bv, v, DMODEL, DMODEL, DMODEL, DMODEL, 0, 0, 0, 1.0f);

    // 3) scale_norm over full D (in place)
    scalenorm_kernel<<<ROWS, 256>>>(q, q, sc);
    scalenorm_kernel<<<ROWS, 256>>>(k, k, sc);
    scalenorm_kernel<<<ROWS, 256>>>(v, v, sc);

    // 3b) V^T hi/lo split
    vt_convert<<<dim3(TSEQ / 64, 1, NGRP), 256>>>(v, vh, vl);

    // 4) S = Q K^T / 8 into attn region (batched over 32 groups)
    dim3 gs(TSEQ / 128, TSEQ / 128, NGRP);  // (16, 16, 32)
    gemm_mma<<<gs, 256, GEMM_SMEM>>>(q, k, nullptr, attn, DK, DK, DK, TSEQ,
                                     GRP_STRIDE, GRP_STRIDE, ATTN_PER_G, 0.125f);

    // 5) softmax in place
    softmax_kernel<<<NGRP * TSEQ, 256>>>(attn);

    // 6) O = attn @ V with scatter epilogue
    pv_mma<<<dim3(TSEQ / 128, 1, NGRP), 256, PV_SMEM>>>(attn, vh, vl, out);
}